// round 3
// baseline (speedup 1.0000x reference)
#include <cuda_runtime.h>
#include <cuda_bf16.h>
#include <math.h>

#define Nn 10000
#define Ee 320000
#define ET (Ee + Nn)   // edges + self loops
#define DH 256
#define DOUT 64

#define CAP  96        // rows cached in smem per node
#define SCAP 1024      // scores cached in smem per node
#define SMEM_GAT ((CAP * DH + 2 * DH + SCAP) * 4)

// ---------------- device scratch (no cudaMalloc allowed) ----------------
__device__ float g_xl[Nn * DH];
__device__ float g_xr[Nn * DH];
__device__ float g_h[Nn * DH];
__device__ float g_logits[Nn * DOUT];
__device__ float g_scores[ET];
__device__ int   g_csr_src[ET];
__device__ int   g_cnt[Nn];
__device__ int   g_row_ptr[Nn + 1];
__device__ int   g_row_off[Nn];
__device__ int   g_flag_i64[1];

// ---------------- combined zero + dtype detect ----------------
__global__ void k_zero_detect(const int* ei32) {
    int i = blockIdx.x * blockDim.x + threadIdx.x;
    if (i < Nn) g_cnt[i] = 0;
    if (i == 0) {
        int all0 = 1;
        for (int j = 0; j < 64; ++j) {
            if (ei32[2 * j + 1] != 0) { all0 = 0; break; }
        }
        g_flag_i64[0] = all0;
    }
}

__device__ __forceinline__ int edge_val(const void* ei, long long idx, int is64) {
    if (is64) return (int)((const long long*)ei)[idx];
    return ((const int*)ei)[idx];
}

__global__ void k_hist(const void* ei) {
    int e = blockIdx.x * blockDim.x + threadIdx.x;
    if (e >= ET) return;
    int is64 = g_flag_i64[0];
    int dst = (e >= Ee) ? (e - Ee) : edge_val(ei, (long long)Ee + e, is64);
    atomicAdd(&g_cnt[dst], 1);
}

// hierarchical shuffle scan: 1024 threads x 10 elems
__global__ __launch_bounds__(1024) void k_scan() {
    __shared__ int wsum[32];
    int tid = threadIdx.x;
    int lane = tid & 31, w = tid >> 5;
    int base = tid * 10;
    int c[10];
    int s = 0;
#pragma unroll
    for (int i = 0; i < 10; ++i) {
        int idx = base + i;
        c[i] = (idx < Nn) ? g_cnt[idx] : 0;
        s += c[i];
    }
    int incl = s;
#pragma unroll
    for (int o = 1; o < 32; o <<= 1) {
        int v = __shfl_up_sync(0xffffffffu, incl, o);
        if (lane >= o) incl += v;
    }
    if (lane == 31) wsum[w] = incl;
    __syncthreads();
    if (w == 0) {
        int wi = wsum[lane];
#pragma unroll
        for (int o = 1; o < 32; o <<= 1) {
            int t = __shfl_up_sync(0xffffffffu, wi, o);
            if (lane >= o) wi += t;
        }
        wsum[lane] = wi;
    }
    __syncthreads();
    int excl = incl - s + (w > 0 ? wsum[w - 1] : 0);
    int run = excl;
#pragma unroll
    for (int i = 0; i < 10; ++i) {
        int idx = base + i;
        if (idx < Nn) {
            g_row_ptr[idx] = run;
            g_row_off[idx] = run;
            run += c[i];
        }
    }
    if (tid == 0) g_row_ptr[Nn] = ET;
}

__global__ void k_scatter(const void* ei) {
    int e = blockIdx.x * blockDim.x + threadIdx.x;
    if (e >= ET) return;
    int is64 = g_flag_i64[0];
    int src, dst;
    if (e >= Ee) {
        src = dst = e - Ee;
    } else {
        src = edge_val(ei, (long long)e, is64);
        dst = edge_val(ei, (long long)Ee + e, is64);
    }
    int pos = atomicAdd(&g_row_off[dst], 1);
    g_csr_src[pos] = src;
}

// ---------------- TF32 tensor-core GEMM ----------------
__device__ __forceinline__ unsigned f2tf32(float v) {
    unsigned o;
    asm volatile("cvt.rna.tf32.f32 %0, %1;" : "=r"(o) : "f"(v));
    return o;
}

// core body shared by single and dual variants
template<int BN, int WARPS_M, int MT>
__device__ __forceinline__ void gemm_body(
    const float* __restrict__ A, const float* __restrict__ B,
    const float* __restrict__ bias, float* __restrict__ C,
    int M, int Nc, int K, int row0, int col0)
{
    constexpr int BM = 128;
    constexpr int BK = 32;
    constexpr int NT = 4;
    constexpr int ASTR = 36;
    constexpr int BSTR = BN + 8;

    __shared__ unsigned As[BM][ASTR];
    __shared__ unsigned Bs[BK][BSTR];

    int tid = threadIdx.x;
    int lane = tid & 31;
    int wid = tid >> 5;
    int gid = lane >> 2;
    int tin = lane & 3;

    int wm = wid % WARPS_M;
    int wn = wid / WARPS_M;
    int mbase = wm * (MT * 16);
    int nbase = wn * 32;

    float c[MT][NT][4];
#pragma unroll
    for (int i = 0; i < MT; ++i)
#pragma unroll
        for (int j = 0; j < NT; ++j)
#pragma unroll
            for (int q = 0; q < 4; ++q) c[i][j][q] = 0.f;

    constexpr int AF4 = (BM * BK) / 4 / 256;
    constexpr int BF4 = (BK * BN) / 4 / 256;
    constexpr int BROWF4 = BN / 4;

    for (int k0 = 0; k0 < K; k0 += BK) {
#pragma unroll
        for (int i = 0; i < AF4; ++i) {
            int idx = tid + i * 256;
            int r = idx >> 3;
            int c4 = (idx & 7) * 4;
            float4 v = make_float4(0.f, 0.f, 0.f, 0.f);
            if (row0 + r < M)
                v = *(const float4*)(A + (size_t)(row0 + r) * K + k0 + c4);
            uint4 t;
            t.x = f2tf32(v.x); t.y = f2tf32(v.y);
            t.z = f2tf32(v.z); t.w = f2tf32(v.w);
            *(uint4*)&As[r][c4] = t;
        }
#pragma unroll
        for (int i = 0; i < BF4; ++i) {
            int idx = tid + i * 256;
            int r = idx / BROWF4;
            int c4 = (idx % BROWF4) * 4;
            float4 v = *(const float4*)(B + (size_t)(k0 + r) * Nc + col0 + c4);
            uint4 t;
            t.x = f2tf32(v.x); t.y = f2tf32(v.y);
            t.z = f2tf32(v.z); t.w = f2tf32(v.w);
            *(uint4*)&Bs[r][c4] = t;
        }
        __syncthreads();

#pragma unroll
        for (int kk = 0; kk < BK; kk += 8) {
            unsigned a[MT][4];
#pragma unroll
            for (int mt = 0; mt < MT; ++mt) {
                int r = mbase + mt * 16 + gid;
                a[mt][0] = As[r][kk + tin];
                a[mt][1] = As[r + 8][kk + tin];
                a[mt][2] = As[r][kk + tin + 4];
                a[mt][3] = As[r + 8][kk + tin + 4];
            }
            unsigned b[NT][2];
#pragma unroll
            for (int nt = 0; nt < NT; ++nt) {
                int n = nbase + nt * 8 + gid;
                b[nt][0] = Bs[kk + tin][n];
                b[nt][1] = Bs[kk + tin + 4][n];
            }
#pragma unroll
            for (int mt = 0; mt < MT; ++mt)
#pragma unroll
                for (int nt = 0; nt < NT; ++nt) {
                    asm volatile(
                        "mma.sync.aligned.m16n8k8.row.col.f32.tf32.tf32.f32 "
                        "{%0,%1,%2,%3}, {%4,%5,%6,%7}, {%8,%9}, {%0,%1,%2,%3};\n"
                        : "+f"(c[mt][nt][0]), "+f"(c[mt][nt][1]),
                          "+f"(c[mt][nt][2]), "+f"(c[mt][nt][3])
                        : "r"(a[mt][0]), "r"(a[mt][1]), "r"(a[mt][2]), "r"(a[mt][3]),
                          "r"(b[nt][0]), "r"(b[nt][1]));
                }
        }
        __syncthreads();
    }

#pragma unroll
    for (int mt = 0; mt < MT; ++mt) {
        int r0 = row0 + mbase + mt * 16 + gid;
        int r1 = r0 + 8;
#pragma unroll
        for (int nt = 0; nt < NT; ++nt) {
            int col = col0 + nbase + nt * 8 + tin * 2;
            float b0 = bias[col], b1 = bias[col + 1];
            if (r0 < M) {
                float2 o = make_float2(c[mt][nt][0] + b0, c[mt][nt][1] + b1);
                *(float2*)(C + (size_t)r0 * Nc + col) = o;
            }
            if (r1 < M) {
                float2 o = make_float2(c[mt][nt][2] + b0, c[mt][nt][3] + b1);
                *(float2*)(C + (size_t)r1 * Nc + col) = o;
            }
        }
    }
}

// dual: computes A@Bl+biasl -> Cl and A@Br+biasr -> Cr in one launch
__global__ __launch_bounds__(256) void k_gemm_tf32_dual(
    const float* __restrict__ A,
    const float* __restrict__ Bl, const float* __restrict__ biasl, float* __restrict__ Cl,
    const float* __restrict__ Br, const float* __restrict__ biasr, float* __restrict__ Cr,
    int M, int Nc, int K)
{
    int half = blockIdx.x >> 1;
    int bx = blockIdx.x & 1;
    const float* B = half ? Br : Bl;
    const float* bias = half ? biasr : biasl;
    float* C = half ? Cr : Cl;
    gemm_body<128, 2, 4>(A, B, bias, C, M, Nc, K,
                         blockIdx.y * 128, bx * 128);
}

__global__ __launch_bounds__(256) void k_gemm_tf32_head(
    const float* __restrict__ A, const float* __restrict__ B,
    const float* __restrict__ bias, float* __restrict__ C,
    int M, int Nc, int K)
{
    gemm_body<64, 4, 2>(A, B, bias, C, M, Nc, K, blockIdx.y * 128, blockIdx.x * 64);
}

// ---------------- GATv2 layer (per-node block, smem row cache) ----------------
__device__ __forceinline__ float warp_sum(float v) {
#pragma unroll
    for (int o = 16; o > 0; o >>= 1) v += __shfl_xor_sync(0xffffffffu, v, o);
    return v;
}

__global__ __launch_bounds__(256) void k_gat_layer(
    const float* __restrict__ xl, const float* __restrict__ xr,
    const float* __restrict__ att, const float* __restrict__ bias,
    float* __restrict__ out, int applyRelu)
{
    extern __shared__ float sm[];
    float* s_cache = sm;                       // CAP * DH
    float* s_xr    = sm + CAP * DH;            // DH
    float* s_att   = s_xr + DH;                // DH
    float* s_sc    = s_att + DH;               // SCAP
    __shared__ float s_red[8];
    __shared__ float s_m, s_inv;

    int node = blockIdx.x;
    int tid = threadIdx.x;
    int lane = tid & 31, w = tid >> 5;

    s_xr[tid]  = xr[(size_t)node * DH + tid];
    s_att[tid] = att[tid];
    __syncthreads();

    int beg = g_row_ptr[node];
    int end = g_row_ptr[node + 1];
    int deg = end - beg;

    // Phase A: warp-per-edge scores; cache gathered rows in smem
    float wmax = -INFINITY;
    for (int e = beg + w; e < end; e += 8) {
        int i = e - beg;
        int src = g_csr_src[e];
        const float* xs = xl + (size_t)src * DH;
        bool cache = (i < CAP);
        float p = 0.f;
#pragma unroll
        for (int j = 0; j < 8; ++j) {
            int d = lane + j * 32;
            float v = xs[d];
            if (cache) s_cache[i * DH + d] = v;
            float t = v + s_xr[d];
            t = (t > 0.f) ? t : 0.2f * t;
            p = fmaf(s_att[d], t, p);
        }
        p = warp_sum(p);
        if (lane == 0) {
            if (i < SCAP) s_sc[i] = p;
            else          g_scores[e] = p;
        }
        wmax = fmaxf(wmax, p);
    }
    if (lane == 0) s_red[w] = wmax;
    __syncthreads();
    if (tid == 0) {
        float m = s_red[0];
#pragma unroll
        for (int i = 1; i < 8; ++i) m = fmaxf(m, s_red[i]);
        s_m = m;
    }
    __syncthreads();
    float m = s_m;

    // Phase A2: exp + sum
    float ps = 0.f;
    for (int i = tid; i < deg; i += 256) {
        float sc = (i < SCAP) ? s_sc[i] : g_scores[beg + i];
        float es = expf(sc - m);
        if (i < SCAP) s_sc[i] = es;
        else          g_scores[beg + i] = es;
        ps += es;
    }
    ps = warp_sum(ps);
    __syncthreads();
    if (lane == 0) s_red[w] = ps;
    __syncthreads();
    if (tid == 0) {
        float s = 0.f;
#pragma unroll
        for (int i = 0; i < 8; ++i) s += s_red[i];
        s_inv = 1.f / s;
    }
    __syncthreads();
    float inv = s_inv;

    // Phase B: thread-per-dim aggregation from smem cache
    float acc = 0.f;
    int cend = (deg < CAP) ? deg : CAP;
    int i = 0;
#pragma unroll 1
    for (; i + 4 <= cend; i += 4) {
        float a0 = s_sc[i + 0], a1 = s_sc[i + 1];
        float a2 = s_sc[i + 2], a3 = s_sc[i + 3];
        float v0 = s_cache[(i + 0) * DH + tid];
        float v1 = s_cache[(i + 1) * DH + tid];
        float v2 = s_cache[(i + 2) * DH + tid];
        float v3 = s_cache[(i + 3) * DH + tid];
        acc = fmaf(a0, v0, acc);
        acc = fmaf(a1, v1, acc);
        acc = fmaf(a2, v2, acc);
        acc = fmaf(a3, v3, acc);
    }
    for (; i < cend; ++i)
        acc = fmaf(s_sc[i], s_cache[i * DH + tid], acc);
    for (; i < deg; ++i) {   // rare overflow path
        float a = (i < SCAP) ? s_sc[i] : g_scores[beg + i];
        acc = fmaf(a, xl[(size_t)g_csr_src[beg + i] * DH + tid], acc);
    }

    float r = acc * inv + bias[tid];
    if (applyRelu) r = fmaxf(r, 0.f);
    out[(size_t)node * DH + tid] = r;
}

// ---------------- log_softmax over 64-dim rows ----------------
__global__ __launch_bounds__(256) void k_logsoftmax(const float* __restrict__ in,
                                                    float* __restrict__ out) {
    int row = blockIdx.x * 8 + (threadIdx.x >> 5);
    if (row >= Nn) return;
    int lane = threadIdx.x & 31;
    float v0 = in[(size_t)row * DOUT + lane];
    float v1 = in[(size_t)row * DOUT + 32 + lane];
    float m = fmaxf(v0, v1);
#pragma unroll
    for (int o = 16; o > 0; o >>= 1) m = fmaxf(m, __shfl_xor_sync(0xffffffffu, m, o));
    float s = expf(v0 - m) + expf(v1 - m);
    s = warp_sum(s);
    float lse = m + logf(s);
    out[(size_t)row * DOUT + lane]       = v0 - lse;
    out[(size_t)row * DOUT + 32 + lane]  = v1 - lse;
}

// ---------------- launch ----------------
extern "C" void kernel_launch(void* const* d_in, const int* in_sizes, int n_in,
                              void* d_out, int out_size) {
    const float* x    = (const float*)d_in[0];
    const float* W1l  = (const float*)d_in[1];
    const float* b1l  = (const float*)d_in[2];
    const float* W1r  = (const float*)d_in[3];
    const float* b1r  = (const float*)d_in[4];
    const float* att1 = (const float*)d_in[5];
    const float* bias1= (const float*)d_in[6];
    const float* W2l  = (const float*)d_in[7];
    const float* b2l  = (const float*)d_in[8];
    const float* W2r  = (const float*)d_in[9];
    const float* b2r  = (const float*)d_in[10];
    const float* att2 = (const float*)d_in[11];
    const float* bias2= (const float*)d_in[12];
    const float* Wout = (const float*)d_in[13];
    const float* bout = (const float*)d_in[14];
    const void*  ei   = d_in[15];
    float* out = (float*)d_out;

    float *xl, *xr, *h, *logits;
    cudaGetSymbolAddress((void**)&xl, g_xl);
    cudaGetSymbolAddress((void**)&xr, g_xr);
    cudaGetSymbolAddress((void**)&h,  g_h);
    cudaGetSymbolAddress((void**)&logits, g_logits);

    static int smem_set = 0;
    if (!smem_set) {
        cudaFuncSetAttribute(k_gat_layer,
                             cudaFuncAttributeMaxDynamicSharedMemorySize, SMEM_GAT);
        smem_set = 1;
    }

    // CSR build
    k_zero_detect<<<(Nn + 255) / 256, 256>>>((const int*)ei);
    k_hist<<<(ET + 255) / 256, 256>>>(ei);
    k_scan<<<1, 1024>>>();
    k_scatter<<<(ET + 255) / 256, 256>>>(ei);

    dim3 gDual(4, (Nn + 127) / 128);
    dim3 gOut(1, (Nn + 127) / 128);

    // layer 1
    k_gemm_tf32_dual<<<gDual, 256>>>(x, W1l, b1l, xl, W1r, b1r, xr, Nn, DH, DH);
    k_gat_layer<<<Nn, 256, SMEM_GAT>>>(xl, xr, att1, bias1, h, 1);

    // layer 2
    k_gemm_tf32_dual<<<gDual, 256>>>(h, W2l, b2l, xl, W2r, b2r, xr, Nn, DH, DH);
    k_gat_layer<<<Nn, 256, SMEM_GAT>>>(xl, xr, att2, bias2, h, 1);

    // output head
    k_gemm_tf32_head<<<gOut, 256>>>(h, Wout, bout, logits, Nn, DOUT, DH);
    k_logsoftmax<<<(Nn + 7) / 8, 256>>>(logits, out);
}

// round 4
// speedup vs baseline: 1.7622x; 1.7622x over previous
#include <cuda_runtime.h>
#include <cuda_bf16.h>
#include <math.h>

#define Nn 10000
#define Ee 320000
#define ET (Ee + Nn)   // edges + self loops
#define DH 256
#define DOUT 64

// ---------------- device scratch (no cudaMalloc allowed) ----------------
__device__ float g_xl[Nn * DH];
__device__ float g_xr[Nn * DH];
__device__ float g_h[Nn * DH];
__device__ int   g_csr_src[ET];
__device__ int   g_cnt[Nn];
__device__ int   g_row_ptr[Nn + 1];
__device__ int   g_row_off[Nn];
__device__ int   g_flag_i64[1];

// ---------------- combined zero + dtype detect ----------------
__global__ void k_zero_detect(const int* ei32) {
    int i = blockIdx.x * blockDim.x + threadIdx.x;
    if (i < Nn) g_cnt[i] = 0;
    if (i == 0) {
        int all0 = 1;
        for (int j = 0; j < 64; ++j) {
            if (ei32[2 * j + 1] != 0) { all0 = 0; break; }
        }
        g_flag_i64[0] = all0;
    }
}

__device__ __forceinline__ int edge_val(const void* ei, long long idx, int is64) {
    if (is64) return (int)((const long long*)ei)[idx];
    return ((const int*)ei)[idx];
}

__global__ void k_hist(const void* ei) {
    int e = blockIdx.x * blockDim.x + threadIdx.x;
    if (e >= ET) return;
    int is64 = g_flag_i64[0];
    int dst = (e >= Ee) ? (e - Ee) : edge_val(ei, (long long)Ee + e, is64);
    atomicAdd(&g_cnt[dst], 1);
}

// hierarchical shuffle scan: 1024 threads x 10 elems
__global__ __launch_bounds__(1024) void k_scan() {
    __shared__ int wsum[32];
    int tid = threadIdx.x;
    int lane = tid & 31, w = tid >> 5;
    int base = tid * 10;
    int c[10];
    int s = 0;
#pragma unroll
    for (int i = 0; i < 10; ++i) {
        int idx = base + i;
        c[i] = (idx < Nn) ? g_cnt[idx] : 0;
        s += c[i];
    }
    int incl = s;
#pragma unroll
    for (int o = 1; o < 32; o <<= 1) {
        int v = __shfl_up_sync(0xffffffffu, incl, o);
        if (lane >= o) incl += v;
    }
    if (lane == 31) wsum[w] = incl;
    __syncthreads();
    if (w == 0) {
        int wi = wsum[lane];
#pragma unroll
        for (int o = 1; o < 32; o <<= 1) {
            int t = __shfl_up_sync(0xffffffffu, wi, o);
            if (lane >= o) wi += t;
        }
        wsum[lane] = wi;
    }
    __syncthreads();
    int excl = incl - s + (w > 0 ? wsum[w - 1] : 0);
    int run = excl;
#pragma unroll
    for (int i = 0; i < 10; ++i) {
        int idx = base + i;
        if (idx < Nn) {
            g_row_ptr[idx] = run;
            g_row_off[idx] = run;
            run += c[i];
        }
    }
    if (tid == 0) g_row_ptr[Nn] = ET;
}

__global__ void k_scatter(const void* ei) {
    int e = blockIdx.x * blockDim.x + threadIdx.x;
    if (e >= ET) return;
    int is64 = g_flag_i64[0];
    int src, dst;
    if (e >= Ee) {
        src = dst = e - Ee;
    } else {
        src = edge_val(ei, (long long)e, is64);
        dst = edge_val(ei, (long long)Ee + e, is64);
    }
    int pos = atomicAdd(&g_row_off[dst], 1);
    g_csr_src[pos] = src;
}

// ---------------- TF32 tensor-core GEMM ----------------
__device__ __forceinline__ unsigned f2tf32(float v) {
    unsigned o;
    asm volatile("cvt.rna.tf32.f32 %0, %1;" : "=r"(o) : "f"(v));
    return o;
}

template<int BN, int WARPS_M, int MT>
__device__ __forceinline__ void gemm_body(
    const float* __restrict__ A, const float* __restrict__ B,
    const float* __restrict__ bias, float* __restrict__ C,
    int M, int Nc, int K, int row0, int col0)
{
    constexpr int BM = 128;
    constexpr int BK = 32;
    constexpr int NT = 4;
    constexpr int ASTR = 36;
    constexpr int BSTR = BN + 8;

    __shared__ unsigned As[BM][ASTR];
    __shared__ unsigned Bs[BK][BSTR];

    int tid = threadIdx.x;
    int lane = tid & 31;
    int wid = tid >> 5;
    int gid = lane >> 2;
    int tin = lane & 3;

    int wm = wid % WARPS_M;
    int wn = wid / WARPS_M;
    int mbase = wm * (MT * 16);
    int nbase = wn * 32;

    float c[MT][NT][4];
#pragma unroll
    for (int i = 0; i < MT; ++i)
#pragma unroll
        for (int j = 0; j < NT; ++j)
#pragma unroll
            for (int q = 0; q < 4; ++q) c[i][j][q] = 0.f;

    constexpr int AF4 = (BM * BK) / 4 / 256;
    constexpr int BF4 = (BK * BN) / 4 / 256;
    constexpr int BROWF4 = BN / 4;

    for (int k0 = 0; k0 < K; k0 += BK) {
#pragma unroll
        for (int i = 0; i < AF4; ++i) {
            int idx = tid + i * 256;
            int r = idx >> 3;
            int c4 = (idx & 7) * 4;
            float4 v = make_float4(0.f, 0.f, 0.f, 0.f);
            if (row0 + r < M)
                v = *(const float4*)(A + (size_t)(row0 + r) * K + k0 + c4);
            uint4 t;
            t.x = f2tf32(v.x); t.y = f2tf32(v.y);
            t.z = f2tf32(v.z); t.w = f2tf32(v.w);
            *(uint4*)&As[r][c4] = t;
        }
#pragma unroll
        for (int i = 0; i < BF4; ++i) {
            int idx = tid + i * 256;
            int r = idx / BROWF4;
            int c4 = (idx % BROWF4) * 4;
            float4 v = *(const float4*)(B + (size_t)(k0 + r) * Nc + col0 + c4);
            uint4 t;
            t.x = f2tf32(v.x); t.y = f2tf32(v.y);
            t.z = f2tf32(v.z); t.w = f2tf32(v.w);
            *(uint4*)&Bs[r][c4] = t;
        }
        __syncthreads();

#pragma unroll
        for (int kk = 0; kk < BK; kk += 8) {
            unsigned a[MT][4];
#pragma unroll
            for (int mt = 0; mt < MT; ++mt) {
                int r = mbase + mt * 16 + gid;
                a[mt][0] = As[r][kk + tin];
                a[mt][1] = As[r + 8][kk + tin];
                a[mt][2] = As[r][kk + tin + 4];
                a[mt][3] = As[r + 8][kk + tin + 4];
            }
            unsigned b[NT][2];
#pragma unroll
            for (int nt = 0; nt < NT; ++nt) {
                int n = nbase + nt * 8 + gid;
                b[nt][0] = Bs[kk + tin][n];
                b[nt][1] = Bs[kk + tin + 4][n];
            }
#pragma unroll
            for (int mt = 0; mt < MT; ++mt)
#pragma unroll
                for (int nt = 0; nt < NT; ++nt) {
                    asm volatile(
                        "mma.sync.aligned.m16n8k8.row.col.f32.tf32.tf32.f32 "
                        "{%0,%1,%2,%3}, {%4,%5,%6,%7}, {%8,%9}, {%0,%1,%2,%3};\n"
                        : "+f"(c[mt][nt][0]), "+f"(c[mt][nt][1]),
                          "+f"(c[mt][nt][2]), "+f"(c[mt][nt][3])
                        : "r"(a[mt][0]), "r"(a[mt][1]), "r"(a[mt][2]), "r"(a[mt][3]),
                          "r"(b[nt][0]), "r"(b[nt][1]));
                }
        }
        __syncthreads();
    }

#pragma unroll
    for (int mt = 0; mt < MT; ++mt) {
        int r0 = row0 + mbase + mt * 16 + gid;
        int r1 = r0 + 8;
#pragma unroll
        for (int nt = 0; nt < NT; ++nt) {
            int col = col0 + nbase + nt * 8 + tin * 2;
            float b0 = bias[col], b1 = bias[col + 1];
            if (r0 < M) {
                float2 o = make_float2(c[mt][nt][0] + b0, c[mt][nt][1] + b1);
                *(float2*)(C + (size_t)r0 * Nc + col) = o;
            }
            if (r1 < M) {
                float2 o = make_float2(c[mt][nt][2] + b0, c[mt][nt][3] + b1);
                *(float2*)(C + (size_t)r1 * Nc + col) = o;
            }
        }
    }
}

// dual: A@Bl+biasl -> Cl and A@Br+biasr -> Cr in one launch
__global__ __launch_bounds__(256) void k_gemm_tf32_dual(
    const float* __restrict__ A,
    const float* __restrict__ Bl, const float* __restrict__ biasl, float* __restrict__ Cl,
    const float* __restrict__ Br, const float* __restrict__ biasr, float* __restrict__ Cr,
    int M, int Nc, int K)
{
    int half = blockIdx.x >> 1;
    int bx = blockIdx.x & 1;
    const float* B = half ? Br : Bl;
    const float* bias = half ? biasr : biasl;
    float* C = half ? Cr : Cl;
    gemm_body<128, 2, 4>(A, B, bias, C, M, Nc, K,
                         blockIdx.y * 128, bx * 128);
}

// ---------------- head GEMM fused with log_softmax ----------------
// BM=128, BN=64 = DOUT: each block owns full output rows.
__global__ __launch_bounds__(256) void k_head_fused(
    const float* __restrict__ A, const float* __restrict__ B,
    const float* __restrict__ bias, float* __restrict__ out, int M, int K)
{
    constexpr int BM = 128, BK = 32, BN = 64;
    constexpr int WARPS_M = 4, MT = 2, NT = 4;
    constexpr int ASTR = 36, BSTR = BN + 8;
    constexpr int LSTR = 66;

    __shared__ unsigned As[BM][ASTR];
    __shared__ unsigned Bs[BK][BSTR];
    __shared__ float s_logits[BM * LSTR];

    int tid = threadIdx.x;
    int lane = tid & 31;
    int wid = tid >> 5;
    int gid = lane >> 2;
    int tin = lane & 3;

    int wm = wid % WARPS_M;
    int wn = wid / WARPS_M;
    int mbase = wm * (MT * 16);
    int nbase = wn * 32;
    int row0 = blockIdx.x * BM;

    float c[MT][NT][4];
#pragma unroll
    for (int i = 0; i < MT; ++i)
#pragma unroll
        for (int j = 0; j < NT; ++j)
#pragma unroll
            for (int q = 0; q < 4; ++q) c[i][j][q] = 0.f;

    constexpr int AF4 = (BM * BK) / 4 / 256;
    constexpr int BF4 = (BK * BN) / 4 / 256;
    constexpr int BROWF4 = BN / 4;

    for (int k0 = 0; k0 < K; k0 += BK) {
#pragma unroll
        for (int i = 0; i < AF4; ++i) {
            int idx = tid + i * 256;
            int r = idx >> 3;
            int c4 = (idx & 7) * 4;
            float4 v = make_float4(0.f, 0.f, 0.f, 0.f);
            if (row0 + r < M)
                v = *(const float4*)(A + (size_t)(row0 + r) * K + k0 + c4);
            uint4 t;
            t.x = f2tf32(v.x); t.y = f2tf32(v.y);
            t.z = f2tf32(v.z); t.w = f2tf32(v.w);
            *(uint4*)&As[r][c4] = t;
        }
#pragma unroll
        for (int i = 0; i < BF4; ++i) {
            int idx = tid + i * 256;
            int r = idx / BROWF4;
            int c4 = (idx % BROWF4) * 4;
            float4 v = *(const float4*)(B + (size_t)(k0 + r) * BN + c4);
            uint4 t;
            t.x = f2tf32(v.x); t.y = f2tf32(v.y);
            t.z = f2tf32(v.z); t.w = f2tf32(v.w);
            *(uint4*)&Bs[r][c4] = t;
        }
        __syncthreads();

#pragma unroll
        for (int kk = 0; kk < BK; kk += 8) {
            unsigned a[MT][4];
#pragma unroll
            for (int mt = 0; mt < MT; ++mt) {
                int r = mbase + mt * 16 + gid;
                a[mt][0] = As[r][kk + tin];
                a[mt][1] = As[r + 8][kk + tin];
                a[mt][2] = As[r][kk + tin + 4];
                a[mt][3] = As[r + 8][kk + tin + 4];
            }
            unsigned b[NT][2];
#pragma unroll
            for (int nt = 0; nt < NT; ++nt) {
                int n = nbase + nt * 8 + gid;
                b[nt][0] = Bs[kk + tin][n];
                b[nt][1] = Bs[kk + tin + 4][n];
            }
#pragma unroll
            for (int mt = 0; mt < MT; ++mt)
#pragma unroll
                for (int nt = 0; nt < NT; ++nt) {
                    asm volatile(
                        "mma.sync.aligned.m16n8k8.row.col.f32.tf32.tf32.f32 "
                        "{%0,%1,%2,%3}, {%4,%5,%6,%7}, {%8,%9}, {%0,%1,%2,%3};\n"
                        : "+f"(c[mt][nt][0]), "+f"(c[mt][nt][1]),
                          "+f"(c[mt][nt][2]), "+f"(c[mt][nt][3])
                        : "r"(a[mt][0]), "r"(a[mt][1]), "r"(a[mt][2]), "r"(a[mt][3]),
                          "r"(b[nt][0]), "r"(b[nt][1]));
                }
        }
        __syncthreads();
    }

    // epilogue -> smem logits
#pragma unroll
    for (int mt = 0; mt < MT; ++mt) {
        int r0 = mbase + mt * 16 + gid;
        int r1 = r0 + 8;
#pragma unroll
        for (int nt = 0; nt < NT; ++nt) {
            int col = nbase + nt * 8 + tin * 2;
            float b0 = bias[col], b1 = bias[col + 1];
            *(float2*)&s_logits[r0 * LSTR + col] =
                make_float2(c[mt][nt][0] + b0, c[mt][nt][1] + b1);
            *(float2*)&s_logits[r1 * LSTR + col] =
                make_float2(c[mt][nt][2] + b0, c[mt][nt][3] + b1);
        }
    }
    __syncthreads();

    // log_softmax: warp w handles rows w*16 .. w*16+15
    for (int r = wid * 16; r < wid * 16 + 16; ++r) {
        int node = row0 + r;
        if (node >= M) break;
        float v0 = s_logits[r * LSTR + lane];
        float v1 = s_logits[r * LSTR + 32 + lane];
        float m = fmaxf(v0, v1);
#pragma unroll
        for (int o = 16; o > 0; o >>= 1)
            m = fmaxf(m, __shfl_xor_sync(0xffffffffu, m, o));
        float s = expf(v0 - m) + expf(v1 - m);
#pragma unroll
        for (int o = 16; o > 0; o >>= 1)
            s += __shfl_xor_sync(0xffffffffu, s, o);
        float lse = m + logf(s);
        out[(size_t)node * DOUT + lane]      = v0 - lse;
        out[(size_t)node * DOUT + 32 + lane] = v1 - lse;
    }
}

// ---------------- GATv2 layer: online softmax, single gather ----------------
__device__ __forceinline__ float warp_sum(float v) {
#pragma unroll
    for (int o = 16; o > 0; o >>= 1) v += __shfl_xor_sync(0xffffffffu, v, o);
    return v;
}

__device__ __forceinline__ float lrelu(float v) {
    return (v > 0.f) ? v : 0.2f * v;
}

__global__ __launch_bounds__(256) void k_gat_layer(
    const float* __restrict__ xl, const float* __restrict__ xr,
    const float* __restrict__ att, const float* __restrict__ bias,
    float* __restrict__ out, int applyRelu)
{
    __shared__ float s_xr[DH];
    __shared__ float s_att[DH];
    __shared__ float s_part[8 * DH];
    __shared__ float s_mw[8], s_sw[8];
    __shared__ float s_m, s_inv;

    int node = blockIdx.x;
    int tid = threadIdx.x;
    int lane = tid & 31, w = tid >> 5;

    s_xr[tid]  = xr[(size_t)node * DH + tid];
    s_att[tid] = att[tid];
    __syncthreads();

    // lane owns dims lane*4+q and 128+lane*4+q
    float4 xrA = ((const float4*)s_xr)[lane];
    float4 xrB = ((const float4*)s_xr)[lane + 32];
    float4 atA = ((const float4*)s_att)[lane];
    float4 atB = ((const float4*)s_att)[lane + 32];

    int beg = g_row_ptr[node];
    int end = g_row_ptr[node + 1];

    float m_w = -INFINITY, s_w = 0.f;
    float a0 = 0.f, a1 = 0.f, a2 = 0.f, a3 = 0.f;
    float a4 = 0.f, a5 = 0.f, a6 = 0.f, a7 = 0.f;

    for (int e = beg + w; e < end; e += 8) {
        int src = g_csr_src[e];
        const float4* xs4 = (const float4*)(xl + (size_t)src * DH);
        float4 vA = xs4[lane];
        float4 vB = xs4[lane + 32];

        float p = atA.x * lrelu(vA.x + xrA.x);
        p = fmaf(atA.y, lrelu(vA.y + xrA.y), p);
        p = fmaf(atA.z, lrelu(vA.z + xrA.z), p);
        p = fmaf(atA.w, lrelu(vA.w + xrA.w), p);
        p = fmaf(atB.x, lrelu(vB.x + xrB.x), p);
        p = fmaf(atB.y, lrelu(vB.y + xrB.y), p);
        p = fmaf(atB.z, lrelu(vB.z + xrB.z), p);
        p = fmaf(atB.w, lrelu(vB.w + xrB.w), p);
        p = warp_sum(p);

        float nm = fmaxf(m_w, p);
        float c1 = expf(m_w - nm);   // 0 on first iteration (m_w = -inf)
        float c2 = expf(p - nm);
        s_w = s_w * c1 + c2;
        a0 = fmaf(a0, c1, c2 * vA.x);
        a1 = fmaf(a1, c1, c2 * vA.y);
        a2 = fmaf(a2, c1, c2 * vA.z);
        a3 = fmaf(a3, c1, c2 * vA.w);
        a4 = fmaf(a4, c1, c2 * vB.x);
        a5 = fmaf(a5, c1, c2 * vB.y);
        a6 = fmaf(a6, c1, c2 * vB.z);
        a7 = fmaf(a7, c1, c2 * vB.w);
        m_w = nm;
    }

    if (lane == 0) { s_mw[w] = m_w; s_sw[w] = s_w; }
    __syncthreads();
    if (tid == 0) {
        float m = s_mw[0];
#pragma unroll
        for (int i = 1; i < 8; ++i) m = fmaxf(m, s_mw[i]);
        float s = 0.f;
#pragma unroll
        for (int i = 0; i < 8; ++i) s += s_sw[i] * expf(s_mw[i] - m);
        s_m = m;
        s_inv = 1.f / s;
    }
    __syncthreads();

    float scale = expf(m_w - s_m);   // 0 for warps with no edges
    ((float4*)s_part)[w * 64 + lane] =
        make_float4(a0 * scale, a1 * scale, a2 * scale, a3 * scale);
    ((float4*)s_part)[w * 64 + 32 + lane] =
        make_float4(a4 * scale, a5 * scale, a6 * scale, a7 * scale);
    __syncthreads();

    float r = 0.f;
#pragma unroll
    for (int i = 0; i < 8; ++i) r += s_part[i * DH + tid];
    r = r * s_inv + bias[tid];
    if (applyRelu) r = fmaxf(r, 0.f);
    out[(size_t)node * DH + tid] = r;
}

// ---------------- launch ----------------
extern "C" void kernel_launch(void* const* d_in, const int* in_sizes, int n_in,
                              void* d_out, int out_size) {
    const float* x    = (const float*)d_in[0];
    const float* W1l  = (const float*)d_in[1];
    const float* b1l  = (const float*)d_in[2];
    const float* W1r  = (const float*)d_in[3];
    const float* b1r  = (const float*)d_in[4];
    const float* att1 = (const float*)d_in[5];
    const float* bias1= (const float*)d_in[6];
    const float* W2l  = (const float*)d_in[7];
    const float* b2l  = (const float*)d_in[8];
    const float* W2r  = (const float*)d_in[9];
    const float* b2r  = (const float*)d_in[10];
    const float* att2 = (const float*)d_in[11];
    const float* bias2= (const float*)d_in[12];
    const float* Wout = (const float*)d_in[13];
    const float* bout = (const float*)d_in[14];
    const void*  ei   = d_in[15];
    float* out = (float*)d_out;

    float *xl, *xr, *h;
    cudaGetSymbolAddress((void**)&xl, g_xl);
    cudaGetSymbolAddress((void**)&xr, g_xr);
    cudaGetSymbolAddress((void**)&h,  g_h);

    // CSR build
    k_zero_detect<<<(Nn + 255) / 256, 256>>>((const int*)ei);
    k_hist<<<(ET + 255) / 256, 256>>>(ei);
    k_scan<<<1, 1024>>>();
    k_scatter<<<(ET + 255) / 256, 256>>>(ei);

    dim3 gDual(4, (Nn + 127) / 128);

    // layer 1
    k_gemm_tf32_dual<<<gDual, 256>>>(x, W1l, b1l, xl, W1r, b1r, xr, Nn, DH, DH);
    k_gat_layer<<<Nn, 256>>>(xl, xr, att1, bias1, h, 1);

    // layer 2
    k_gemm_tf32_dual<<<gDual, 256>>>(h, W2l, b2l, xl, W2r, b2r, xr, Nn, DH, DH);
    k_gat_layer<<<Nn, 256>>>(xl, xr, att2, bias2, h, 1);

    // output head + log_softmax fused
    k_head_fused<<<(Nn + 127) / 128, 256>>>(h, Wout, bout, out, Nn, DH);
}

// round 5
// speedup vs baseline: 1.9224x; 1.0909x over previous
#include <cuda_runtime.h>
#include <cuda_fp16.h>
#include <math.h>

#define Nn 10000
#define Ee 320000
#define ET (Ee + Nn)   // edges + self loops
#define DH 256
#define DOUT 64

// ---------------- device scratch (no cudaMalloc allowed) ----------------
__device__ __half g_xl[Nn * DH];
__device__ __half g_xr[Nn * DH];
__device__ float  g_h[Nn * DH];
__device__ int    g_csr_src[ET];
__device__ int    g_cnt[Nn];
__device__ int    g_row_ptr[Nn + 1];
__device__ int    g_row_off[Nn];
__device__ int    g_flag_i64[1];

// ---------------- combined zero + dtype detect ----------------
__global__ void k_zero_detect(const int* ei32) {
    int i = blockIdx.x * blockDim.x + threadIdx.x;
    if (i < Nn) g_cnt[i] = 0;
    if (i == 0) {
        int all0 = 1;
        for (int j = 0; j < 64; ++j) {
            if (ei32[2 * j + 1] != 0) { all0 = 0; break; }
        }
        g_flag_i64[0] = all0;
    }
}

__device__ __forceinline__ int edge_val(const void* ei, long long idx, int is64) {
    if (is64) return (int)((const long long*)ei)[idx];
    return ((const int*)ei)[idx];
}

__global__ void k_hist(const void* ei) {
    int e = blockIdx.x * blockDim.x + threadIdx.x;
    if (e >= ET) return;
    int is64 = g_flag_i64[0];
    int dst = (e >= Ee) ? (e - Ee) : edge_val(ei, (long long)Ee + e, is64);
    atomicAdd(&g_cnt[dst], 1);
}

// hierarchical shuffle scan: 1024 threads x 10 elems
__global__ __launch_bounds__(1024) void k_scan() {
    __shared__ int wsum[32];
    int tid = threadIdx.x;
    int lane = tid & 31, w = tid >> 5;
    int base = tid * 10;
    int c[10];
    int s = 0;
#pragma unroll
    for (int i = 0; i < 10; ++i) {
        int idx = base + i;
        c[i] = (idx < Nn) ? g_cnt[idx] : 0;
        s += c[i];
    }
    int incl = s;
#pragma unroll
    for (int o = 1; o < 32; o <<= 1) {
        int v = __shfl_up_sync(0xffffffffu, incl, o);
        if (lane >= o) incl += v;
    }
    if (lane == 31) wsum[w] = incl;
    __syncthreads();
    if (w == 0) {
        int wi = wsum[lane];
#pragma unroll
        for (int o = 1; o < 32; o <<= 1) {
            int t = __shfl_up_sync(0xffffffffu, wi, o);
            if (lane >= o) wi += t;
        }
        wsum[lane] = wi;
    }
    __syncthreads();
    int excl = incl - s + (w > 0 ? wsum[w - 1] : 0);
    int run = excl;
#pragma unroll
    for (int i = 0; i < 10; ++i) {
        int idx = base + i;
        if (idx < Nn) {
            g_row_ptr[idx] = run;
            g_row_off[idx] = run;
            run += c[i];
        }
    }
    if (tid == 0) g_row_ptr[Nn] = ET;
}

__global__ void k_scatter(const void* ei) {
    int e = blockIdx.x * blockDim.x + threadIdx.x;
    if (e >= ET) return;
    int is64 = g_flag_i64[0];
    int src, dst;
    if (e >= Ee) {
        src = dst = e - Ee;
    } else {
        src = edge_val(ei, (long long)e, is64);
        dst = edge_val(ei, (long long)Ee + e, is64);
    }
    int pos = atomicAdd(&g_row_off[dst], 1);
    g_csr_src[pos] = src;
}

// ---------------- TF32 tensor-core GEMM ----------------
__device__ __forceinline__ unsigned f2tf32(float v) {
    unsigned o;
    asm volatile("cvt.rna.tf32.f32 %0, %1;" : "=r"(o) : "f"(v));
    return o;
}

template<int BN, int WARPS_M, int MT, typename OT>
__device__ __forceinline__ void gemm_body(
    const float* __restrict__ A, const float* __restrict__ B,
    const float* __restrict__ bias, OT* __restrict__ C,
    int M, int Nc, int K, int row0, int col0)
{
    constexpr int BM = 128;
    constexpr int BK = 32;
    constexpr int NT = 4;
    constexpr int ASTR = 36;
    constexpr int BSTR = BN + 8;

    __shared__ unsigned As[BM][ASTR];
    __shared__ unsigned Bs[BK][BSTR];

    int tid = threadIdx.x;
    int lane = tid & 31;
    int wid = tid >> 5;
    int gid = lane >> 2;
    int tin = lane & 3;

    int wm = wid % WARPS_M;
    int wn = wid / WARPS_M;
    int mbase = wm * (MT * 16);
    int nbase = wn * 32;

    float c[MT][NT][4];
#pragma unroll
    for (int i = 0; i < MT; ++i)
#pragma unroll
        for (int j = 0; j < NT; ++j)
#pragma unroll
            for (int q = 0; q < 4; ++q) c[i][j][q] = 0.f;

    constexpr int AF4 = (BM * BK) / 4 / 256;
    constexpr int BF4 = (BK * BN) / 4 / 256;
    constexpr int BROWF4 = BN / 4;

    for (int k0 = 0; k0 < K; k0 += BK) {
#pragma unroll
        for (int i = 0; i < AF4; ++i) {
            int idx = tid + i * 256;
            int r = idx >> 3;
            int c4 = (idx & 7) * 4;
            float4 v = make_float4(0.f, 0.f, 0.f, 0.f);
            if (row0 + r < M)
                v = *(const float4*)(A + (size_t)(row0 + r) * K + k0 + c4);
            uint4 t;
            t.x = f2tf32(v.x); t.y = f2tf32(v.y);
            t.z = f2tf32(v.z); t.w = f2tf32(v.w);
            *(uint4*)&As[r][c4] = t;
        }
#pragma unroll
        for (int i = 0; i < BF4; ++i) {
            int idx = tid + i * 256;
            int r = idx / BROWF4;
            int c4 = (idx % BROWF4) * 4;
            float4 v = *(const float4*)(B + (size_t)(k0 + r) * Nc + col0 + c4);
            uint4 t;
            t.x = f2tf32(v.x); t.y = f2tf32(v.y);
            t.z = f2tf32(v.z); t.w = f2tf32(v.w);
            *(uint4*)&Bs[r][c4] = t;
        }
        __syncthreads();

#pragma unroll
        for (int kk = 0; kk < BK; kk += 8) {
            unsigned a[MT][4];
#pragma unroll
            for (int mt = 0; mt < MT; ++mt) {
                int r = mbase + mt * 16 + gid;
                a[mt][0] = As[r][kk + tin];
                a[mt][1] = As[r + 8][kk + tin];
                a[mt][2] = As[r][kk + tin + 4];
                a[mt][3] = As[r + 8][kk + tin + 4];
            }
            unsigned b[NT][2];
#pragma unroll
            for (int nt = 0; nt < NT; ++nt) {
                int n = nbase + nt * 8 + gid;
                b[nt][0] = Bs[kk + tin][n];
                b[nt][1] = Bs[kk + tin + 4][n];
            }
#pragma unroll
            for (int mt = 0; mt < MT; ++mt)
#pragma unroll
                for (int nt = 0; nt < NT; ++nt) {
                    asm volatile(
                        "mma.sync.aligned.m16n8k8.row.col.f32.tf32.tf32.f32 "
                        "{%0,%1,%2,%3}, {%4,%5,%6,%7}, {%8,%9}, {%0,%1,%2,%3};\n"
                        : "+f"(c[mt][nt][0]), "+f"(c[mt][nt][1]),
                          "+f"(c[mt][nt][2]), "+f"(c[mt][nt][3])
                        : "r"(a[mt][0]), "r"(a[mt][1]), "r"(a[mt][2]), "r"(a[mt][3]),
                          "r"(b[nt][0]), "r"(b[nt][1]));
                }
        }
        __syncthreads();
    }

#pragma unroll
    for (int mt = 0; mt < MT; ++mt) {
        int r0 = row0 + mbase + mt * 16 + gid;
        int r1 = r0 + 8;
#pragma unroll
        for (int nt = 0; nt < NT; ++nt) {
            int col = col0 + nbase + nt * 8 + tin * 2;
            float b0 = bias[col], b1 = bias[col + 1];
            if (r0 < M) {
                float v0 = c[mt][nt][0] + b0, v1 = c[mt][nt][1] + b1;
                if constexpr (sizeof(OT) == 2)
                    *(__half2*)(C + (size_t)r0 * Nc + col) = __floats2half2_rn(v0, v1);
                else
                    *(float2*)((float*)C + (size_t)r0 * Nc + col) = make_float2(v0, v1);
            }
            if (r1 < M) {
                float v0 = c[mt][nt][2] + b0, v1 = c[mt][nt][3] + b1;
                if constexpr (sizeof(OT) == 2)
                    *(__half2*)(C + (size_t)r1 * Nc + col) = __floats2half2_rn(v0, v1);
                else
                    *(float2*)((float*)C + (size_t)r1 * Nc + col) = make_float2(v0, v1);
            }
        }
    }
}

// dual: A@Bl+biasl -> Cl (half) and A@Br+biasr -> Cr (half) in one launch
__global__ __launch_bounds__(256) void k_gemm_tf32_dual(
    const float* __restrict__ A,
    const float* __restrict__ Bl, const float* __restrict__ biasl, __half* __restrict__ Cl,
    const float* __restrict__ Br, const float* __restrict__ biasr, __half* __restrict__ Cr,
    int M, int Nc, int K)
{
    int half_sel = blockIdx.x >> 1;
    int bx = blockIdx.x & 1;
    const float* B = half_sel ? Br : Bl;
    const float* bias = half_sel ? biasr : biasl;
    __half* C = half_sel ? Cr : Cl;
    gemm_body<128, 2, 4, __half>(A, B, bias, C, M, Nc, K,
                                 blockIdx.y * 128, bx * 128);
}

// ---------------- head GEMM fused with log_softmax ----------------
__global__ __launch_bounds__(256) void k_head_fused(
    const float* __restrict__ A, const float* __restrict__ B,
    const float* __restrict__ bias, float* __restrict__ out, int M, int K)
{
    constexpr int BM = 128, BK = 32, BN = 64;
    constexpr int WARPS_M = 4, MT = 2, NT = 4;
    constexpr int ASTR = 36, BSTR = BN + 8;
    constexpr int LSTR = 66;

    __shared__ unsigned As[BM][ASTR];
    __shared__ unsigned Bs[BK][BSTR];
    __shared__ float s_logits[BM * LSTR];

    int tid = threadIdx.x;
    int lane = tid & 31;
    int wid = tid >> 5;
    int gid = lane >> 2;
    int tin = lane & 3;

    int wm = wid % WARPS_M;
    int wn = wid / WARPS_M;
    int mbase = wm * (MT * 16);
    int nbase = wn * 32;
    int row0 = blockIdx.x * BM;

    float c[MT][NT][4];
#pragma unroll
    for (int i = 0; i < MT; ++i)
#pragma unroll
        for (int j = 0; j < NT; ++j)
#pragma unroll
            for (int q = 0; q < 4; ++q) c[i][j][q] = 0.f;

    constexpr int AF4 = (BM * BK) / 4 / 256;
    constexpr int BF4 = (BK * BN) / 4 / 256;
    constexpr int BROWF4 = BN / 4;

    for (int k0 = 0; k0 < K; k0 += BK) {
#pragma unroll
        for (int i = 0; i < AF4; ++i) {
            int idx = tid + i * 256;
            int r = idx >> 3;
            int c4 = (idx & 7) * 4;
            float4 v = make_float4(0.f, 0.f, 0.f, 0.f);
            if (row0 + r < M)
                v = *(const float4*)(A + (size_t)(row0 + r) * K + k0 + c4);
            uint4 t;
            t.x = f2tf32(v.x); t.y = f2tf32(v.y);
            t.z = f2tf32(v.z); t.w = f2tf32(v.w);
            *(uint4*)&As[r][c4] = t;
        }
#pragma unroll
        for (int i = 0; i < BF4; ++i) {
            int idx = tid + i * 256;
            int r = idx / BROWF4;
            int c4 = (idx % BROWF4) * 4;
            float4 v = *(const float4*)(B + (size_t)(k0 + r) * BN + c4);
            uint4 t;
            t.x = f2tf32(v.x); t.y = f2tf32(v.y);
            t.z = f2tf32(v.z); t.w = f2tf32(v.w);
            *(uint4*)&Bs[r][c4] = t;
        }
        __syncthreads();

#pragma unroll
        for (int kk = 0; kk < BK; kk += 8) {
            unsigned a[MT][4];
#pragma unroll
            for (int mt = 0; mt < MT; ++mt) {
                int r = mbase + mt * 16 + gid;
                a[mt][0] = As[r][kk + tin];
                a[mt][1] = As[r + 8][kk + tin];
                a[mt][2] = As[r][kk + tin + 4];
                a[mt][3] = As[r + 8][kk + tin + 4];
            }
            unsigned b[NT][2];
#pragma unroll
            for (int nt = 0; nt < NT; ++nt) {
                int n = nbase + nt * 8 + gid;
                b[nt][0] = Bs[kk + tin][n];
                b[nt][1] = Bs[kk + tin + 4][n];
            }
#pragma unroll
            for (int mt = 0; mt < MT; ++mt)
#pragma unroll
                for (int nt = 0; nt < NT; ++nt) {
                    asm volatile(
                        "mma.sync.aligned.m16n8k8.row.col.f32.tf32.tf32.f32 "
                        "{%0,%1,%2,%3}, {%4,%5,%6,%7}, {%8,%9}, {%0,%1,%2,%3};\n"
                        : "+f"(c[mt][nt][0]), "+f"(c[mt][nt][1]),
                          "+f"(c[mt][nt][2]), "+f"(c[mt][nt][3])
                        : "r"(a[mt][0]), "r"(a[mt][1]), "r"(a[mt][2]), "r"(a[mt][3]),
                          "r"(b[nt][0]), "r"(b[nt][1]));
                }
        }
        __syncthreads();
    }

#pragma unroll
    for (int mt = 0; mt < MT; ++mt) {
        int r0 = mbase + mt * 16 + gid;
        int r1 = r0 + 8;
#pragma unroll
        for (int nt = 0; nt < NT; ++nt) {
            int col = nbase + nt * 8 + tin * 2;
            float b0 = bias[col], b1 = bias[col + 1];
            *(float2*)&s_logits[r0 * LSTR + col] =
                make_float2(c[mt][nt][0] + b0, c[mt][nt][1] + b1);
            *(float2*)&s_logits[r1 * LSTR + col] =
                make_float2(c[mt][nt][2] + b0, c[mt][nt][3] + b1);
        }
    }
    __syncthreads();

    for (int r = wid * 16; r < wid * 16 + 16; ++r) {
        int node = row0 + r;
        if (node >= M) break;
        float v0 = s_logits[r * LSTR + lane];
        float v1 = s_logits[r * LSTR + 32 + lane];
        float m = fmaxf(v0, v1);
#pragma unroll
        for (int o = 16; o > 0; o >>= 1)
            m = fmaxf(m, __shfl_xor_sync(0xffffffffu, m, o));
        float s = expf(v0 - m) + expf(v1 - m);
#pragma unroll
        for (int o = 16; o > 0; o >>= 1)
            s += __shfl_xor_sync(0xffffffffu, s, o);
        float lse = m + logf(s);
        out[(size_t)node * DOUT + lane]      = v0 - lse;
        out[(size_t)node * DOUT + 32 + lane] = v1 - lse;
    }
}

// ---------------- GATv2 layer: fp16 gather, online softmax ----------------
__device__ __forceinline__ float warp_sum(float v) {
#pragma unroll
    for (int o = 16; o > 0; o >>= 1) v += __shfl_xor_sync(0xffffffffu, v, o);
    return v;
}

__device__ __forceinline__ float lrelu(float v) {
    return (v > 0.f) ? v : 0.2f * v;
}

__device__ __forceinline__ void unpack8(uint4 u, float* f) {
    float2 p;
    p = __half22float2(*(__half2*)&u.x); f[0] = p.x; f[1] = p.y;
    p = __half22float2(*((__half2*)&u.x + 1)); f[2] = p.x; f[3] = p.y;
    p = __half22float2(*(__half2*)&u.y); f[4] = p.x; f[5] = p.y;
    // note: uint4 = 16B = 8 halves; x holds h0..h1? Actually each unsigned = 2 halves.
}

__global__ __launch_bounds__(256) void k_gat_layer(
    const __half* __restrict__ xl, const __half* __restrict__ xr,
    const float* __restrict__ att, const float* __restrict__ bias,
    float* __restrict__ out, int applyRelu)
{
    __shared__ float s_part[8 * DH];
    __shared__ float s_mw[8], s_sw[8];
    __shared__ float s_m, s_inv;

    int node = blockIdx.x;
    int tid = threadIdx.x;
    int lane = tid & 31, w = tid >> 5;

    // lane owns 8 contiguous dims: d = lane*8 + q
    float xrv[8], atv[8];
    {
        uint4 hx = *(const uint4*)(xr + (size_t)node * DH + lane * 8);
        const unsigned* hu = (const unsigned*)&hx;
#pragma unroll
        for (int q = 0; q < 4; ++q) {
            float2 p = __half22float2(*(const __half2*)&hu[q]);
            xrv[2 * q] = p.x; xrv[2 * q + 1] = p.y;
        }
        float4 a0 = ((const float4*)att)[lane * 2];
        float4 a1 = ((const float4*)att)[lane * 2 + 1];
        atv[0] = a0.x; atv[1] = a0.y; atv[2] = a0.z; atv[3] = a0.w;
        atv[4] = a1.x; atv[5] = a1.y; atv[6] = a1.z; atv[7] = a1.w;
    }

    int beg = g_row_ptr[node];
    int end = g_row_ptr[node + 1];

    float m_w = -INFINITY, s_w = 0.f;
    float acc[8] = {0.f, 0.f, 0.f, 0.f, 0.f, 0.f, 0.f, 0.f};

    for (int e = beg + w; e < end; e += 8) {
        int src = g_csr_src[e];
        uint4 hv = *(const uint4*)(xl + (size_t)src * DH + lane * 8);
        const unsigned* hu = (const unsigned*)&hv;
        float v[8];
#pragma unroll
        for (int q = 0; q < 4; ++q) {
            float2 p = __half22float2(*(const __half2*)&hu[q]);
            v[2 * q] = p.x; v[2 * q + 1] = p.y;
        }

        float p = 0.f;
#pragma unroll
        for (int q = 0; q < 8; ++q)
            p = fmaf(atv[q], lrelu(v[q] + xrv[q]), p);
        p = warp_sum(p);

        float nm = fmaxf(m_w, p);
        float c1 = expf(m_w - nm);
        float c2 = expf(p - nm);
        s_w = s_w * c1 + c2;
#pragma unroll
        for (int q = 0; q < 8; ++q)
            acc[q] = fmaf(acc[q], c1, c2 * v[q]);
        m_w = nm;
    }

    if (lane == 0) { s_mw[w] = m_w; s_sw[w] = s_w; }
    __syncthreads();
    if (tid == 0) {
        float m = s_mw[0];
#pragma unroll
        for (int i = 1; i < 8; ++i) m = fmaxf(m, s_mw[i]);
        float s = 0.f;
#pragma unroll
        for (int i = 0; i < 8; ++i) s += s_sw[i] * expf(s_mw[i] - m);
        s_m = m;
        s_inv = 1.f / s;
    }
    __syncthreads();

    float scale = expf(m_w - s_m);   // 0 for warps with no edges
    {
        float4* dst = (float4*)(s_part + w * DH + lane * 8);
        dst[0] = make_float4(acc[0] * scale, acc[1] * scale, acc[2] * scale, acc[3] * scale);
        dst[1] = make_float4(acc[4] * scale, acc[5] * scale, acc[6] * scale, acc[7] * scale);
    }
    __syncthreads();

    float r = 0.f;
#pragma unroll
    for (int i = 0; i < 8; ++i) r += s_part[i * DH + tid];
    r = r * s_inv + bias[tid];
    if (applyRelu) r = fmaxf(r, 0.f);
    out[(size_t)node * DH + tid] = r;
}

// ---------------- launch ----------------
extern "C" void kernel_launch(void* const* d_in, const int* in_sizes, int n_in,
                              void* d_out, int out_size) {
    const float* x    = (const float*)d_in[0];
    const float* W1l  = (const float*)d_in[1];
    const float* b1l  = (const float*)d_in[2];
    const float* W1r  = (const float*)d_in[3];
    const float* b1r  = (const float*)d_in[4];
    const float* att1 = (const float*)d_in[5];
    const float* bias1= (const float*)d_in[6];
    const float* W2l  = (const float*)d_in[7];
    const float* b2l  = (const float*)d_in[8];
    const float* W2r  = (const float*)d_in[9];
    const float* b2r  = (const float*)d_in[10];
    const float* att2 = (const float*)d_in[11];
    const float* bias2= (const float*)d_in[12];
    const float* Wout = (const float*)d_in[13];
    const float* bout = (const float*)d_in[14];
    const void*  ei   = d_in[15];
    float* out = (float*)d_out;

    __half *xl, *xr;
    float *h;
    cudaGetSymbolAddress((void**)&xl, g_xl);
    cudaGetSymbolAddress((void**)&xr, g_xr);
    cudaGetSymbolAddress((void**)&h,  g_h);

    static cudaStream_t s_csr = nullptr;
    static cudaEvent_t ev_root = nullptr, ev_csr = nullptr;
    if (!s_csr) {
        cudaStreamCreateWithFlags(&s_csr, cudaStreamNonBlocking);
        cudaEventCreateWithFlags(&ev_root, cudaEventDisableTiming);
        cudaEventCreateWithFlags(&ev_csr, cudaEventDisableTiming);
    }

    // fork: CSR build on side stream, concurrent with layer-1 GEMMs
    cudaEventRecord(ev_root, 0);
    cudaStreamWaitEvent(s_csr, ev_root, 0);
    k_zero_detect<<<(Nn + 255) / 256, 256, 0, s_csr>>>((const int*)ei);
    k_hist<<<(ET + 255) / 256, 256, 0, s_csr>>>(ei);
    k_scan<<<1, 1024, 0, s_csr>>>();
    k_scatter<<<(ET + 255) / 256, 256, 0, s_csr>>>(ei);
    cudaEventRecord(ev_csr, s_csr);

    dim3 gDual(4, (Nn + 127) / 128);

    // layer 1 GEMMs (independent of CSR)
    k_gemm_tf32_dual<<<gDual, 256>>>(x, W1l, b1l, xl, W1r, b1r, xr, Nn, DH, DH);

    // join before GAT
    cudaStreamWaitEvent(0, ev_csr, 0);
    k_gat_layer<<<Nn, 256>>>(xl, xr, att1, bias1, h, 1);

    // layer 2
    k_gemm_tf32_dual<<<gDual, 256>>>(h, W2l, b2l, xl, W2r, b2r, xr, Nn, DH, DH);
    k_gat_layer<<<Nn, 256>>>(xl, xr, att2, bias2, h, 1);

    // output head + log_softmax fused
    k_head_fused<<<(Nn + 127) / 128, 256>>>(h, Wout, bout, out, Nn, DH);
}